// round 16
// baseline (speedup 1.0000x reference)
#include <cuda_runtime.h>
#include <math.h>
#include <stdint.h>

#define BB 4
#define SS 4096
#define DD 1024
#define HH 16
#define DH 64
#define BSZ 128
#define NB 32
#define EPSF 1e-4f

// ---------------- scratch ----------------
__device__ float g_angles[BB*SS*HH];
__device__ int   g_idx[BB*SS*HH];
__device__ int   g_inv[BB*SS*HH];
__device__ float g_qk[(size_t)BB*SS*DD];    // SORTED per head
__device__ float g_v [(size_t)BB*SS*DD];    // SORTED per head
__device__ float g_outs[(size_t)BB*SS*DD];
__device__ float g_ch0[BB*SS*HH];

__device__ __forceinline__ float tf32r(float x) {
    uint32_t u;
    asm("cvt.rna.tf32.f32 %0, %1;" : "=r"(u) : "f"(x));
    return __uint_as_float(u);
}
__device__ __forceinline__ uint32_t tf32u(float x) {
    uint32_t u;
    asm("cvt.rna.tf32.f32 %0, %1;" : "=r"(u) : "f"(x));
    return u;
}

__device__ __forceinline__ void mma_tf32(float4& d,
                                         uint32_t a0, uint32_t a1, uint32_t a2, uint32_t a3,
                                         uint32_t b0, uint32_t b1) {
    asm volatile(
        "mma.sync.aligned.m16n8k8.row.col.f32.tf32.tf32.f32 "
        "{%0,%1,%2,%3},{%4,%5,%6,%7},{%8,%9},{%0,%1,%2,%3};"
        : "+f"(d.x), "+f"(d.y), "+f"(d.z), "+f"(d.w)
        : "r"(a0), "r"(a1), "r"(a2), "r"(a3), "r"(b0), "r"(b1));
}

__device__ __forceinline__ void cpa16(uint32_t saddr, const float* g) {
    asm volatile("cp.async.cg.shared.global [%0], [%1], 16;\n" :: "r"(saddr), "l"(g));
}

__device__ __forceinline__ unsigned long long shfl64(unsigned long long v, int lanemask) {
    uint32_t lo = (uint32_t)v, hi = (uint32_t)(v >> 32);
    lo = __shfl_xor_sync(0xffffffffu, lo, lanemask);
    hi = __shfl_xor_sync(0xffffffffu, hi, lanemask);
    return ((unsigned long long)hi << 32) | lo;
}
__device__ __forceinline__ void cswap(unsigned long long& a, unsigned long long& b, bool up) {
    if ((a > b) == up) { unsigned long long t = a; a = b; b = t; }
}

// ---------------- 1) hash v2 (bit-identical chains) ----------------
__global__ void __launch_bounds__(256) hash_kernel(const float* __restrict__ x,
                                                   const float* __restrict__ Wh) {
    __shared__ float4 xs4[32][64];
    __shared__ float  hs[32][33];
    int tid = threadIdx.x;
    int g  = tid & 31;
    int o0 = (tid >> 5) * 4;
    int tok0 = blockIdx.x * 32;
    const float4* xbase = (const float4*)(x + (size_t)tok0 * DD);
    const float4* w4 = (const float4*)Wh;

    float acc0 = 0.f, acc1 = 0.f, acc2 = 0.f, acc3 = 0.f;
    for (int c = 0; c < 4; c++) {
        __syncthreads();
        #pragma unroll
        for (int i = 0; i < 8; i++) {
            int idx = tid + i*256;
            int r = idx >> 6, k4 = idx & 63;
            xs4[r][k4 ^ (r & 7)] = xbase[(size_t)r*(DD/4) + c*64 + k4];
        }
        __syncthreads();
        const float4* wr0 = w4 + (size_t)(o0+0)*(DD/4) + c*64;
        const float4* wr1 = w4 + (size_t)(o0+1)*(DD/4) + c*64;
        const float4* wr2 = w4 + (size_t)(o0+2)*(DD/4) + c*64;
        const float4* wr3 = w4 + (size_t)(o0+3)*(DD/4) + c*64;
        #pragma unroll 8
        for (int k4 = 0; k4 < 64; k4++) {
            float4 xv = xs4[g][k4 ^ (g & 7)];
            float4 w0 = __ldg(wr0 + k4);
            float4 w1 = __ldg(wr1 + k4);
            float4 w2 = __ldg(wr2 + k4);
            float4 w3 = __ldg(wr3 + k4);
            acc0 = fmaf(xv.x, w0.x, acc0); acc0 = fmaf(xv.y, w0.y, acc0);
            acc0 = fmaf(xv.z, w0.z, acc0); acc0 = fmaf(xv.w, w0.w, acc0);
            acc1 = fmaf(xv.x, w1.x, acc1); acc1 = fmaf(xv.y, w1.y, acc1);
            acc1 = fmaf(xv.z, w1.z, acc1); acc1 = fmaf(xv.w, w1.w, acc1);
            acc2 = fmaf(xv.x, w2.x, acc2); acc2 = fmaf(xv.y, w2.y, acc2);
            acc2 = fmaf(xv.z, w2.z, acc2); acc2 = fmaf(xv.w, w2.w, acc2);
            acc3 = fmaf(xv.x, w3.x, acc3); acc3 = fmaf(xv.y, w3.y, acc3);
            acc3 = fmaf(xv.z, w3.z, acc3); acc3 = fmaf(xv.w, w3.w, acc3);
        }
    }
    hs[g][o0]   = acc0;
    hs[g][o0+1] = acc1;
    hs[g][o0+2] = acc2;
    hs[g][o0+3] = acc3;
    __syncthreads();
    for (int i = tid; i < 32*HH; i += 256) {
        int gg = i >> 4, hh = i & 15;
        float h0 = hs[gg][2*hh], h1 = hs[gg][2*hh+1];
        g_angles[(size_t)(tok0 + gg)*HH + hh] = __fdiv_rn(h0, h1 + EPSF);
    }
}

// ---------------- 2) bitonic argsort v2 (register/shuffle resident) ----------------
__global__ void __launch_bounds__(1024) sort_kernel() {
    int b = blockIdx.x / HH, h = blockIdx.x % HH;
    __shared__ unsigned long long sk[SS];
    int tid = threadIdx.x;
    int e0 = 4 * tid;

    unsigned long long v[4];
    #pragma unroll
    for (int q = 0; q < 4; q++) {
        int e = e0 + q;
        uint32_t u = __float_as_uint(g_angles[((size_t)b*SS + e)*HH + h]);
        u ^= (u & 0x80000000u) ? 0xFFFFFFFFu : 0x80000000u;
        v[q] = ((unsigned long long)u << 32) | (uint32_t)e;
    }

    for (int k = 2; k <= SS; k <<= 1) {
        int j = k >> 1;
        if (j >= 128) {
            #pragma unroll
            for (int q = 0; q < 4; q++) sk[e0 + q] = v[q];
            __syncthreads();
            for (; j >= 128; j >>= 1) {
                #pragma unroll
                for (int t2 = 0; t2 < 2; t2++) {
                    int i2 = tid + t2*1024;
                    int i = ((i2 & ~(j-1)) << 1) | (i2 & (j-1));
                    int ixj = i + j;
                    bool up = ((i & k) == 0);
                    unsigned long long a = sk[i], c = sk[ixj];
                    if ((a > c) == up) { sk[i] = c; sk[ixj] = a; }
                }
                __syncthreads();
            }
            #pragma unroll
            for (int q = 0; q < 4; q++) v[q] = sk[e0 + q];
        }
        for (; j >= 4; j >>= 1) {
            int pl = j >> 2;
            bool keepmin = (((tid & pl) == 0) == ((e0 & k) == 0));
            #pragma unroll
            for (int q = 0; q < 4; q++) {
                unsigned long long o = shfl64(v[q], pl);
                unsigned long long mn = v[q] < o ? v[q] : o;
                unsigned long long mx = v[q] < o ? o : v[q];
                v[q] = keepmin ? mn : mx;
            }
        }
        if (k >= 4) {
            bool up = ((e0 & k) == 0);
            cswap(v[0], v[2], up);
            cswap(v[1], v[3], up);
        }
        {
            bool up0 = (((e0    ) & k) == 0);
            bool up1 = (((e0 + 2) & k) == 0);
            cswap(v[0], v[1], up0);
            cswap(v[2], v[3], up1);
        }
    }

    #pragma unroll
    for (int q = 0; q < 4; q++) {
        int e = e0 + q;
        int orig = (int)(v[q] & 0xFFFFFFFFu);
        g_idx[((size_t)b*SS + e)*HH + h]    = orig;
        g_inv[((size_t)b*SS + orig)*HH + h] = e;
    }
}

// ---------------- 3) TF32 GEMM v4: 128x128x32, 3-stage cp.async, 1 barrier/iter ----
#define AST 36

__global__ void __launch_bounds__(256, 2) gemm3(const float* __restrict__ A,
                                                const float* __restrict__ W0,
                                                const float* __restrict__ b0,
                                                float* __restrict__ C0,
                                                const float* __restrict__ W1,
                                                const float* __restrict__ b1,
                                                float* __restrict__ C1,
                                                int split, int N, int K, int mode) {
    extern __shared__ float smem[];
    float* As = smem;                   // [3][128][AST]
    float* Bs = smem + 3*128*AST;       // [3][128][AST]

    const float* W; const float* bias; float* C;
    int bx = blockIdx.x;
    if (bx < split) { W = W0; bias = b0; C = C0; }
    else            { W = W1; bias = b1; C = C1; bx -= split; }
    int bm = blockIdx.y * 128, bn = bx * 128;

    int tid  = threadIdx.x;
    int lane = tid & 31, wid = tid >> 5;
    int g = lane >> 2, tg = lane & 3;
    int warp_m = (wid & 1) * 64;
    int warp_n = (wid >> 1) * 32;

    float4 acc[4][4];
    #pragma unroll
    for (int i = 0; i < 4; i++)
        #pragma unroll
        for (int j = 0; j < 4; j++) acc[i][j] = make_float4(0.f,0.f,0.f,0.f);

    auto load_tile = [&](int k0, int buf) {
        uint32_t abase = (uint32_t)__cvta_generic_to_shared(As + buf*128*AST);
        uint32_t bbase = (uint32_t)__cvta_generic_to_shared(Bs + buf*128*AST);
        #pragma unroll
        for (int i = 0; i < 4; i++) {
            int idx = tid + i*256;
            int r = idx >> 3, c4 = (idx & 7) * 4;
            cpa16(abase + (r*AST + c4)*4, A + (size_t)(bm + r)*K + k0 + c4);
            cpa16(bbase + (r*AST + c4)*4, W + (size_t)(bn + r)*K + k0 + c4);
        }
        asm volatile("cp.async.commit_group;\n");
    };

    int nkt = K / 32;
    load_tile(0, 0);
    load_tile(32, 1);

    for (int kt = 0; kt < nkt; kt++) {
        if (kt + 1 < nkt) {
            asm volatile("cp.async.wait_group 1;\n");   // tile kt landed
        } else {
            asm volatile("cp.async.wait_group 0;\n");
        }
        __syncthreads();   // also protects buffer (kt-1)%3 reuse below

        if (kt + 2 < nkt) load_tile((kt + 2) * 32, (kt + 2) % 3);

        int cur = kt % 3;
        const float* Ab = As + cur*128*AST;
        const float* Bb = Bs + cur*128*AST;
        #pragma unroll
        for (int ks = 0; ks < 4; ks++) {
            int kc = ks * 8;
            uint32_t a[4][4], b[4][2];
            #pragma unroll
            for (int mt = 0; mt < 4; mt++) {
                int r0 = warp_m + mt*16;
                a[mt][0] = tf32u(Ab[(r0+g  )*AST + kc+tg  ]);
                a[mt][1] = tf32u(Ab[(r0+g+8)*AST + kc+tg  ]);
                a[mt][2] = tf32u(Ab[(r0+g  )*AST + kc+tg+4]);
                a[mt][3] = tf32u(Ab[(r0+g+8)*AST + kc+tg+4]);
            }
            #pragma unroll
            for (int nt = 0; nt < 4; nt++) {
                int n0 = warp_n + nt*8;
                b[nt][0] = tf32u(Bb[(n0+g)*AST + kc+tg  ]);
                b[nt][1] = tf32u(Bb[(n0+g)*AST + kc+tg+4]);
            }
            #pragma unroll
            for (int mt = 0; mt < 4; mt++)
                #pragma unroll
                for (int nt = 0; nt < 4; nt++)
                    mma_tf32(acc[mt][nt], a[mt][0],a[mt][1],a[mt][2],a[mt][3],
                             b[nt][0], b[nt][1]);
        }
    }

    if (mode == 0) {
        #pragma unroll
        for (int mt = 0; mt < 4; mt++) {
            int r0 = bm + warp_m + mt*16 + g;
            #pragma unroll
            for (int nt = 0; nt < 4; nt++) {
                int col = bn + warp_n + nt*8 + 2*tg;
                float bx2 = __ldg(bias + col), by = __ldg(bias + col + 1);
                float4 c = acc[mt][nt];
                *(float2*)(C + (size_t)r0*N + col)     = make_float2(c.x + bx2, c.y + by);
                *(float2*)(C + (size_t)(r0+8)*N + col) = make_float2(c.z + bx2, c.w + by);
            }
        }
    } else {
        int hsel = (bn + warp_n) >> 6;
        #pragma unroll
        for (int mt = 0; mt < 4; mt++) {
            int r0 = bm + warp_m + mt*16 + g;
            int r1 = r0 + 8;
            int p0 = g_inv[(size_t)r0*HH + hsel];
            int p1 = g_inv[(size_t)r1*HH + hsel];
            size_t o0 = ((size_t)(r0 & ~(SS-1)) + p0) * (size_t)N;
            size_t o1 = ((size_t)(r1 & ~(SS-1)) + p1) * (size_t)N;
            #pragma unroll
            for (int nt = 0; nt < 4; nt++) {
                int col = bn + warp_n + nt*8 + 2*tg;
                float bx2 = __ldg(bias + col), by = __ldg(bias + col + 1);
                float4 c = acc[mt][nt];
                *(float2*)(C + o0 + col) = make_float2(c.x + bx2, c.y + by);
                *(float2*)(C + o1 + col) = make_float2(c.z + bx2, c.w + by);
            }
        }
    }
}

// ---------------- 4) attention: register softmax, Q doubles as K-half0 ----------------
#define SST 260
#define QST 68
#define VST 72

__global__ void __launch_bounds__(512) attn_kernel() {
    extern __shared__ float smem[];
    float* sS = smem;                            // 128 x SST (P)
    float* sQ = smem + 128*SST;                  // 128 x QST (Q == K half0)
    float* sK = sQ + 128*QST;                    // 128 x QST (K half1)
    float* sV = sQ;                              // 256 x VST overlay
    float* red = smem + 128*SST + 2*128*QST + 1024;  // 512 floats

    int tid = threadIdx.x;
    int lane = tid & 31, wid = tid >> 5;
    int g = lane >> 2, tg = lane & 3;
    int mt = wid & 7;
    int ng = wid >> 3;
    int warp_m = mt * 16;
    int warp_n = ng * 64;
    int warp_nV = ng * 32;

    int n = blockIdx.x, h = blockIdx.y, b = blockIdx.z;
    int base = n * BSZ;
    const float* qkp = g_qk + (size_t)b*SS*DD + h*DH;
    const float* vp  = g_v  + (size_t)b*SS*DD + h*DH;
    const float scale = 0.03125f;

    uint32_t sqb = (uint32_t)__cvta_generic_to_shared(sQ);
    uint32_t skb = (uint32_t)__cvta_generic_to_shared(sK);
    uint32_t svb = (uint32_t)__cvta_generic_to_shared(sV);

    for (int p = tid; p < 128*16; p += 512) {
        int r = p >> 4, seg = p & 15;
        cpa16(sqb + (r*QST + seg*4)*4, qkp + (size_t)(base + r)*DD + seg*4);
    }
    for (int p = tid; p < 128*16; p += 512) {
        int r = p >> 4, seg = p & 15;
        cpa16(skb + (r*QST + seg*4)*4,
              qkp + (size_t)((base + 128 + r) & (SS-1))*DD + seg*4);
    }
    asm volatile("cp.async.commit_group;\n");
    asm volatile("cp.async.wait_group 0;\n");
    __syncthreads();

    float4 acc[2][8];
    #pragma unroll
    for (int i = 0; i < 2; i++)
        #pragma unroll
        for (int j = 0; j < 8; j++) acc[i][j] = make_float4(0.f,0.f,0.f,0.f);

    #pragma unroll 1
    for (int hf = 0; hf < 2; hf++) {
        const float* Bsrc = hf ? sK : sQ;
        #pragma unroll
        for (int ks = 0; ks < 8; ks++) {
            int kc = ks * 8;
            uint32_t a[4], bfr[8][2];
            a[0] = tf32u(sQ[(warp_m+g  )*QST + kc+tg  ]);
            a[1] = tf32u(sQ[(warp_m+g+8)*QST + kc+tg  ]);
            a[2] = tf32u(sQ[(warp_m+g  )*QST + kc+tg+4]);
            a[3] = tf32u(sQ[(warp_m+g+8)*QST + kc+tg+4]);
            #pragma unroll
            for (int nt = 0; nt < 8; nt++) {
                int n0 = warp_n + nt*8;
                bfr[nt][0] = tf32u(Bsrc[(n0+g)*QST + kc+tg  ]);
                bfr[nt][1] = tf32u(Bsrc[(n0+g)*QST + kc+tg+4]);
            }
            #pragma unroll
            for (int nt = 0; nt < 8; nt++)
                mma_tf32(acc[hf][nt], a[0],a[1],a[2],a[3], bfr[nt][0], bfr[nt][1]);
        }
    }

    int i0 = warp_m + g;
    #pragma unroll
    for (int hf = 0; hf < 2; hf++) {
        #pragma unroll
        for (int nt = 0; nt < 8; nt++) {
            int j0 = warp_n + nt*8 + 2*tg;
            float4 c = acc[hf][nt];
            c.x *= scale; c.y *= scale; c.z *= scale; c.w *= scale;
            if (hf == 0) {
                if (j0   == i0  ) c.x = -INFINITY;
                if (j0+1 == i0  ) c.y = -INFINITY;
                if (j0   == i0+8) c.z = -INFINITY;
                if (j0+1 == i0+8) c.w = -INFINITY;
            }
            acc[hf][nt] = c;
        }
    }
    __syncthreads();

    for (int p = tid; p < 256*16; p += 512) {
        int j = p >> 4, seg = p & 15;
        cpa16(svb + (j*VST + seg*4)*4, vp + (size_t)((base + j) & (SS-1))*DD + seg*4);
    }
    asm volatile("cp.async.commit_group;\n");

    float* redM = red;
    float* redS = red + 256;
    float m0 = -INFINITY, m1 = -INFINITY;
    #pragma unroll
    for (int hf = 0; hf < 2; hf++)
        #pragma unroll
        for (int nt = 0; nt < 8; nt++) {
            float4 c = acc[hf][nt];
            m0 = fmaxf(m0, fmaxf(c.x, c.y));
            m1 = fmaxf(m1, fmaxf(c.z, c.w));
        }
    m0 = fmaxf(m0, __shfl_xor_sync(0xffffffffu, m0, 1));
    m0 = fmaxf(m0, __shfl_xor_sync(0xffffffffu, m0, 2));
    m1 = fmaxf(m1, __shfl_xor_sync(0xffffffffu, m1, 1));
    m1 = fmaxf(m1, __shfl_xor_sync(0xffffffffu, m1, 2));
    if (tg == 0) {
        redM[ng*128 + warp_m + g]     = m0;
        redM[ng*128 + warp_m + g + 8] = m1;
    }
    __syncthreads();
    float mg0 = fmaxf(redM[warp_m + g],     redM[128 + warp_m + g]);
    float mg1 = fmaxf(redM[warp_m + g + 8], redM[128 + warp_m + g + 8]);

    float s0 = 0.f, s1 = 0.f;
    #pragma unroll
    for (int hf = 0; hf < 2; hf++)
        #pragma unroll
        for (int nt = 0; nt < 8; nt++) {
            float4 c = acc[hf][nt];
            c.x = __expf(c.x - mg0); c.y = __expf(c.y - mg0);
            c.z = __expf(c.z - mg1); c.w = __expf(c.w - mg1);
            s0 += c.x + c.y; s1 += c.z + c.w;
            acc[hf][nt] = c;
        }
    s0 += __shfl_xor_sync(0xffffffffu, s0, 1);
    s0 += __shfl_xor_sync(0xffffffffu, s0, 2);
    s1 += __shfl_xor_sync(0xffffffffu, s1, 1);
    s1 += __shfl_xor_sync(0xffffffffu, s1, 2);
    if (tg == 0) {
        redS[ng*128 + warp_m + g]     = s0;
        redS[ng*128 + warp_m + g + 8] = s1;
    }
    __syncthreads();
    float inv0 = 1.f / (redS[warp_m + g]     + redS[128 + warp_m + g]);
    float inv1 = 1.f / (redS[warp_m + g + 8] + redS[128 + warp_m + g + 8]);

    #pragma unroll
    for (int hf = 0; hf < 2; hf++)
        #pragma unroll
        for (int nt = 0; nt < 8; nt++) {
            int col = hf*128 + warp_n + nt*8 + 2*tg;
            float4 c = acc[hf][nt];
            *(float2*)&sS[(i0  )*SST + col] = make_float2(tf32r(c.x*inv0), tf32r(c.y*inv0));
            *(float2*)&sS[(i0+8)*SST + col] = make_float2(tf32r(c.z*inv1), tf32r(c.w*inv1));
        }

    asm volatile("cp.async.wait_group 0;\n");
    __syncthreads();

    float4 o[4];
    #pragma unroll
    for (int j = 0; j < 4; j++) o[j] = make_float4(0.f,0.f,0.f,0.f);

    #pragma unroll 4
    for (int ks = 0; ks < 32; ks++) {
        int kc = ks * 8;
        uint32_t a[4], bfr[4][2];
        a[0] = __float_as_uint(sS[(warp_m+g  )*SST + kc+tg  ]);
        a[1] = __float_as_uint(sS[(warp_m+g+8)*SST + kc+tg  ]);
        a[2] = __float_as_uint(sS[(warp_m+g  )*SST + kc+tg+4]);
        a[3] = __float_as_uint(sS[(warp_m+g+8)*SST + kc+tg+4]);
        #pragma unroll
        for (int nt = 0; nt < 4; nt++) {
            int n0 = warp_nV + nt*8;
            bfr[nt][0] = tf32u(sV[(kc+tg  )*VST + n0+g]);
            bfr[nt][1] = tf32u(sV[(kc+tg+4)*VST + n0+g]);
        }
        #pragma unroll
        for (int nt = 0; nt < 4; nt++)
            mma_tf32(o[nt], a[0],a[1],a[2],a[3], bfr[nt][0], bfr[nt][1]);
    }

    float* outp = g_outs + (size_t)b*SS*DD + h*DH;
    {
        int t0 = base + i0;
        #pragma unroll
        for (int nt = 0; nt < 4; nt++) {
            int d0 = warp_nV + nt*8 + 2*tg;
            float4 c = o[nt];
            *(float2*)(outp + (size_t)t0*DD + d0)     = make_float2(c.x, c.y);
            *(float2*)(outp + (size_t)(t0+8)*DD + d0) = make_float2(c.z, c.w);
            if (d0 == 0) {
                g_ch0[((size_t)b*SS + t0  )*HH + h] = c.x;
                g_ch0[((size_t)b*SS + t0+8)*HH + h] = c.z;
            }
        }
    }
}

// ---------------- 5) feature-0-only inverse scatter ----------------
__global__ void __launch_bounds__(256) scatter_kernel() {
    int i = blockIdx.x*256 + threadIdx.x;
    if (i >= BB*SS*HH) return;
    int h = i % HH;
    int b = i / (SS*HH);
    int p = g_idx[i];
    g_outs[((size_t)b*SS + p)*DD + h*DH] = g_ch0[i];
}

// ---------------- launch ----------------
extern "C" void kernel_launch(void* const* d_in, const int* in_sizes, int n_in,
                              void* d_out, int out_size) {
    const float* x  = (const float*)d_in[0];
    const float* Wh = (const float*)d_in[1];
    const float* Wq = (const float*)d_in[2];
    const float* bq = (const float*)d_in[3];
    const float* Wv = (const float*)d_in[4];
    const float* bv = (const float*)d_in[5];
    const float* Wo = (const float*)d_in[6];
    const float* bo = (const float*)d_in[7];
    float* out = (float*)d_out;

    float* qkp; cudaGetSymbolAddress((void**)&qkp, g_qk);
    float* vp;  cudaGetSymbolAddress((void**)&vp,  g_v);
    float* osp; cudaGetSymbolAddress((void**)&osp, g_outs);

    const int M = BB*SS;

    hash_kernel<<<M/32, 256>>>(x, Wh);
    sort_kernel<<<BB*HH, 1024>>>();

    size_t gsmem = (size_t)(6*128*AST) * sizeof(float);   // 110,592 B (3 stages A+B)
    cudaFuncSetAttribute(gemm3, cudaFuncAttributeMaxDynamicSharedMemorySize, (int)gsmem);
    gemm3<<<dim3(16, M/128), 256, gsmem>>>(x, Wq, bq, qkp, Wv, bv, vp, 8, DD, DD, 1);

    size_t asmem = (size_t)(128*SST + 2*128*QST + 1024 + 512) * sizeof(float);
    cudaFuncSetAttribute(attn_kernel, cudaFuncAttributeMaxDynamicSharedMemorySize, (int)asmem);
    dim3 ag(NB, HH, BB);
    attn_kernel<<<ag, 512, asmem>>>();

    scatter_kernel<<<(BB*SS*HH + 255)/256, 256>>>();
    gemm3<<<dim3(8, M/128), 256, gsmem>>>(osp, Wo, bo, out, Wo, bo, out, 8, DD, DD, 0);
}

// round 17
// speedup vs baseline: 1.0087x; 1.0087x over previous
#include <cuda_runtime.h>
#include <math.h>
#include <stdint.h>

#define BB 4
#define SS 4096
#define DD 1024
#define HH 16
#define DH 64
#define BSZ 128
#define NB 32
#define EPSF 1e-4f

// ---------------- scratch ----------------
__device__ float g_angles[BB*SS*HH];
__device__ int   g_idx[BB*SS*HH];
__device__ int   g_inv[BB*SS*HH];
__device__ float g_qk[(size_t)BB*SS*DD];    // SORTED per head
__device__ float g_v [(size_t)BB*SS*DD];    // SORTED per head
__device__ float g_outs[(size_t)BB*SS*DD];
__device__ float g_ch0[BB*SS*HH];

__device__ __forceinline__ float tf32r(float x) {
    uint32_t u;
    asm("cvt.rna.tf32.f32 %0, %1;" : "=r"(u) : "f"(x));
    return __uint_as_float(u);
}
__device__ __forceinline__ uint32_t tf32u(float x) {
    uint32_t u;
    asm("cvt.rna.tf32.f32 %0, %1;" : "=r"(u) : "f"(x));
    return u;
}

__device__ __forceinline__ void mma_tf32(float4& d,
                                         uint32_t a0, uint32_t a1, uint32_t a2, uint32_t a3,
                                         uint32_t b0, uint32_t b1) {
    asm volatile(
        "mma.sync.aligned.m16n8k8.row.col.f32.tf32.tf32.f32 "
        "{%0,%1,%2,%3},{%4,%5,%6,%7},{%8,%9},{%0,%1,%2,%3};"
        : "+f"(d.x), "+f"(d.y), "+f"(d.z), "+f"(d.w)
        : "r"(a0), "r"(a1), "r"(a2), "r"(a3), "r"(b0), "r"(b1));
}

__device__ __forceinline__ void cpa16(uint32_t saddr, const float* g) {
    asm volatile("cp.async.cg.shared.global [%0], [%1], 16;\n" :: "r"(saddr), "l"(g));
}

__device__ __forceinline__ unsigned long long shfl64(unsigned long long v, int lanemask) {
    uint32_t lo = (uint32_t)v, hi = (uint32_t)(v >> 32);
    lo = __shfl_xor_sync(0xffffffffu, lo, lanemask);
    hi = __shfl_xor_sync(0xffffffffu, hi, lanemask);
    return ((unsigned long long)hi << 32) | lo;
}
__device__ __forceinline__ void cswap(unsigned long long& a, unsigned long long& b, bool up) {
    if ((a > b) == up) { unsigned long long t = a; a = b; b = t; }
}

// ---------------- 1) hash v2 (bit-identical chains) ----------------
__global__ void __launch_bounds__(256) hash_kernel(const float* __restrict__ x,
                                                   const float* __restrict__ Wh) {
    __shared__ float4 xs4[32][64];
    __shared__ float  hs[32][33];
    int tid = threadIdx.x;
    int g  = tid & 31;
    int o0 = (tid >> 5) * 4;
    int tok0 = blockIdx.x * 32;
    const float4* xbase = (const float4*)(x + (size_t)tok0 * DD);
    const float4* w4 = (const float4*)Wh;

    float acc0 = 0.f, acc1 = 0.f, acc2 = 0.f, acc3 = 0.f;
    for (int c = 0; c < 4; c++) {
        __syncthreads();
        #pragma unroll
        for (int i = 0; i < 8; i++) {
            int idx = tid + i*256;
            int r = idx >> 6, k4 = idx & 63;
            xs4[r][k4 ^ (r & 7)] = xbase[(size_t)r*(DD/4) + c*64 + k4];
        }
        __syncthreads();
        const float4* wr0 = w4 + (size_t)(o0+0)*(DD/4) + c*64;
        const float4* wr1 = w4 + (size_t)(o0+1)*(DD/4) + c*64;
        const float4* wr2 = w4 + (size_t)(o0+2)*(DD/4) + c*64;
        const float4* wr3 = w4 + (size_t)(o0+3)*(DD/4) + c*64;
        #pragma unroll 8
        for (int k4 = 0; k4 < 64; k4++) {
            float4 xv = xs4[g][k4 ^ (g & 7)];
            float4 w0 = __ldg(wr0 + k4);
            float4 w1 = __ldg(wr1 + k4);
            float4 w2 = __ldg(wr2 + k4);
            float4 w3 = __ldg(wr3 + k4);
            acc0 = fmaf(xv.x, w0.x, acc0); acc0 = fmaf(xv.y, w0.y, acc0);
            acc0 = fmaf(xv.z, w0.z, acc0); acc0 = fmaf(xv.w, w0.w, acc0);
            acc1 = fmaf(xv.x, w1.x, acc1); acc1 = fmaf(xv.y, w1.y, acc1);
            acc1 = fmaf(xv.z, w1.z, acc1); acc1 = fmaf(xv.w, w1.w, acc1);
            acc2 = fmaf(xv.x, w2.x, acc2); acc2 = fmaf(xv.y, w2.y, acc2);
            acc2 = fmaf(xv.z, w2.z, acc2); acc2 = fmaf(xv.w, w2.w, acc2);
            acc3 = fmaf(xv.x, w3.x, acc3); acc3 = fmaf(xv.y, w3.y, acc3);
            acc3 = fmaf(xv.z, w3.z, acc3); acc3 = fmaf(xv.w, w3.w, acc3);
        }
    }
    hs[g][o0]   = acc0;
    hs[g][o0+1] = acc1;
    hs[g][o0+2] = acc2;
    hs[g][o0+3] = acc3;
    __syncthreads();
    for (int i = tid; i < 32*HH; i += 256) {
        int gg = i >> 4, hh = i & 15;
        float h0 = hs[gg][2*hh], h1 = hs[gg][2*hh+1];
        g_angles[(size_t)(tok0 + gg)*HH + hh] = __fdiv_rn(h0, h1 + EPSF);
    }
}

// ---------------- 2) bitonic argsort v2 (register/shuffle resident) ----------------
__global__ void __launch_bounds__(1024) sort_kernel() {
    int b = blockIdx.x / HH, h = blockIdx.x % HH;
    __shared__ unsigned long long sk[SS];
    int tid = threadIdx.x;
    int e0 = 4 * tid;

    unsigned long long v[4];
    #pragma unroll
    for (int q = 0; q < 4; q++) {
        int e = e0 + q;
        uint32_t u = __float_as_uint(g_angles[((size_t)b*SS + e)*HH + h]);
        u ^= (u & 0x80000000u) ? 0xFFFFFFFFu : 0x80000000u;
        v[q] = ((unsigned long long)u << 32) | (uint32_t)e;
    }

    for (int k = 2; k <= SS; k <<= 1) {
        int j = k >> 1;
        if (j >= 128) {
            #pragma unroll
            for (int q = 0; q < 4; q++) sk[e0 + q] = v[q];
            __syncthreads();
            for (; j >= 128; j >>= 1) {
                #pragma unroll
                for (int t2 = 0; t2 < 2; t2++) {
                    int i2 = tid + t2*1024;
                    int i = ((i2 & ~(j-1)) << 1) | (i2 & (j-1));
                    int ixj = i + j;
                    bool up = ((i & k) == 0);
                    unsigned long long a = sk[i], c = sk[ixj];
                    if ((a > c) == up) { sk[i] = c; sk[ixj] = a; }
                }
                __syncthreads();
            }
            #pragma unroll
            for (int q = 0; q < 4; q++) v[q] = sk[e0 + q];
        }
        for (; j >= 4; j >>= 1) {
            int pl = j >> 2;
            bool keepmin = (((tid & pl) == 0) == ((e0 & k) == 0));
            #pragma unroll
            for (int q = 0; q < 4; q++) {
                unsigned long long o = shfl64(v[q], pl);
                unsigned long long mn = v[q] < o ? v[q] : o;
                unsigned long long mx = v[q] < o ? o : v[q];
                v[q] = keepmin ? mn : mx;
            }
        }
        if (k >= 4) {
            bool up = ((e0 & k) == 0);
            cswap(v[0], v[2], up);
            cswap(v[1], v[3], up);
        }
        {
            bool up0 = (((e0    ) & k) == 0);
            bool up1 = (((e0 + 2) & k) == 0);
            cswap(v[0], v[1], up0);
            cswap(v[2], v[3], up1);
        }
    }

    #pragma unroll
    for (int q = 0; q < 4; q++) {
        int e = e0 + q;
        int orig = (int)(v[q] & 0xFFFFFFFFu);
        g_idx[((size_t)b*SS + e)*HH + h]    = orig;
        g_inv[((size_t)b*SS + orig)*HH + h] = e;
    }
}

// ---------------- 3) TF32 GEMM: 128x128x32, 2-stage cp.async (R15 version) ----------
#define AST 36

__global__ void __launch_bounds__(256, 2) gemm3(const float* __restrict__ A,
                                                const float* __restrict__ W0,
                                                const float* __restrict__ b0,
                                                float* __restrict__ C0,
                                                const float* __restrict__ W1,
                                                const float* __restrict__ b1,
                                                float* __restrict__ C1,
                                                int split, int N, int K, int mode) {
    extern __shared__ float smem[];
    float* As = smem;
    float* Bs = smem + 2*128*AST;

    const float* W; const float* bias; float* C;
    int bx = blockIdx.x;
    if (bx < split) { W = W0; bias = b0; C = C0; }
    else            { W = W1; bias = b1; C = C1; bx -= split; }
    int bm = blockIdx.y * 128, bn = bx * 128;

    int tid  = threadIdx.x;
    int lane = tid & 31, wid = tid >> 5;
    int g = lane >> 2, tg = lane & 3;
    int warp_m = (wid & 1) * 64;
    int warp_n = (wid >> 1) * 32;

    float4 acc[4][4];
    #pragma unroll
    for (int i = 0; i < 4; i++)
        #pragma unroll
        for (int j = 0; j < 4; j++) acc[i][j] = make_float4(0.f,0.f,0.f,0.f);

    auto load_tile = [&](int k0, int buf) {
        uint32_t abase = (uint32_t)__cvta_generic_to_shared(As + buf*128*AST);
        uint32_t bbase = (uint32_t)__cvta_generic_to_shared(Bs + buf*128*AST);
        #pragma unroll
        for (int i = 0; i < 4; i++) {
            int idx = tid + i*256;
            int r = idx >> 3, c4 = (idx & 7) * 4;
            cpa16(abase + (r*AST + c4)*4, A + (size_t)(bm + r)*K + k0 + c4);
            cpa16(bbase + (r*AST + c4)*4, W + (size_t)(bn + r)*K + k0 + c4);
        }
        asm volatile("cp.async.commit_group;\n");
    };

    load_tile(0, 0);

    int nkt = K / 32;
    for (int kt = 0; kt < nkt; kt++) {
        int cur = kt & 1;
        if (kt + 1 < nkt) {
            load_tile((kt + 1) * 32, (kt + 1) & 1);
            asm volatile("cp.async.wait_group 1;\n");
        } else {
            asm volatile("cp.async.wait_group 0;\n");
        }
        __syncthreads();

        const float* Ab = As + cur*128*AST;
        const float* Bb = Bs + cur*128*AST;
        #pragma unroll
        for (int ks = 0; ks < 4; ks++) {
            int kc = ks * 8;
            uint32_t a[4][4], b[4][2];
            #pragma unroll
            for (int mt = 0; mt < 4; mt++) {
                int r0 = warp_m + mt*16;
                a[mt][0] = tf32u(Ab[(r0+g  )*AST + kc+tg  ]);
                a[mt][1] = tf32u(Ab[(r0+g+8)*AST + kc+tg  ]);
                a[mt][2] = tf32u(Ab[(r0+g  )*AST + kc+tg+4]);
                a[mt][3] = tf32u(Ab[(r0+g+8)*AST + kc+tg+4]);
            }
            #pragma unroll
            for (int nt = 0; nt < 4; nt++) {
                int n0 = warp_n + nt*8;
                b[nt][0] = tf32u(Bb[(n0+g)*AST + kc+tg  ]);
                b[nt][1] = tf32u(Bb[(n0+g)*AST + kc+tg+4]);
            }
            #pragma unroll
            for (int mt = 0; mt < 4; mt++)
                #pragma unroll
                for (int nt = 0; nt < 4; nt++)
                    mma_tf32(acc[mt][nt], a[mt][0],a[mt][1],a[mt][2],a[mt][3],
                             b[nt][0], b[nt][1]);
        }
        __syncthreads();
    }

    if (mode == 0) {
        #pragma unroll
        for (int mt = 0; mt < 4; mt++) {
            int r0 = bm + warp_m + mt*16 + g;
            #pragma unroll
            for (int nt = 0; nt < 4; nt++) {
                int col = bn + warp_n + nt*8 + 2*tg;
                float bx2 = __ldg(bias + col), by = __ldg(bias + col + 1);
                float4 c = acc[mt][nt];
                *(float2*)(C + (size_t)r0*N + col)     = make_float2(c.x + bx2, c.y + by);
                *(float2*)(C + (size_t)(r0+8)*N + col) = make_float2(c.z + bx2, c.w + by);
            }
        }
    } else {
        int hsel = (bn + warp_n) >> 6;
        #pragma unroll
        for (int mt = 0; mt < 4; mt++) {
            int r0 = bm + warp_m + mt*16 + g;
            int r1 = r0 + 8;
            int p0 = g_inv[(size_t)r0*HH + hsel];
            int p1 = g_inv[(size_t)r1*HH + hsel];
            size_t o0 = ((size_t)(r0 & ~(SS-1)) + p0) * (size_t)N;
            size_t o1 = ((size_t)(r1 & ~(SS-1)) + p1) * (size_t)N;
            #pragma unroll
            for (int nt = 0; nt < 4; nt++) {
                int col = bn + warp_n + nt*8 + 2*tg;
                float bx2 = __ldg(bias + col), by = __ldg(bias + col + 1);
                float4 c = acc[mt][nt];
                *(float2*)(C + o0 + col) = make_float2(c.x + bx2, c.y + by);
                *(float2*)(C + o1 + col) = make_float2(c.z + bx2, c.w + by);
            }
        }
    }
}

// ---------------- 4) attention: register softmax + register-resident PV ----------
#define QST 68
#define VST 72
#define PST 66
// smem (floats): [0, 18432) = Q/K then V overlay; [18432, 26880) = psum; [26880, 27392) = red
#define OVR 18432

__global__ void __launch_bounds__(512) attn_kernel() {
    extern __shared__ float smem[];
    float* sQ = smem;                            // 128 x QST
    float* sK = smem + 128*QST;                  // 128 x QST
    float* sV = smem;                            // 256 x VST overlay (after scores)
    float* ps  = smem + OVR;                     // 128 x PST partial sums
    float* red = smem + OVR + 128*PST;           // 512 floats

    int tid = threadIdx.x;
    int lane = tid & 31, wid = tid >> 5;
    int g = lane >> 2, tg = lane & 3;
    int mt = wid & 7;
    int ng = wid >> 3;                // 0/1 (col group)
    int warp_m = mt * 16;
    int warp_n = ng * 64;             // 64-col slice within each 128-col half

    int n = blockIdx.x, h = blockIdx.y, b = blockIdx.z;
    int base = n * BSZ;
    const float* qkp = g_qk + (size_t)b*SS*DD + h*DH;
    const float* vp  = g_v  + (size_t)b*SS*DD + h*DH;
    const float scale = 0.03125f;

    uint32_t sqb = (uint32_t)__cvta_generic_to_shared(sQ);
    uint32_t skb = (uint32_t)__cvta_generic_to_shared(sK);
    uint32_t svb = (uint32_t)__cvta_generic_to_shared(sV);

    // Q (== K half0) + K half1
    for (int p = tid; p < 128*16; p += 512) {
        int r = p >> 4, seg = p & 15;
        cpa16(sqb + (r*QST + seg*4)*4, qkp + (size_t)(base + r)*DD + seg*4);
    }
    for (int p = tid; p < 128*16; p += 512) {
        int r = p >> 4, seg = p & 15;
        cpa16(skb + (r*QST + seg*4)*4,
              qkp + (size_t)((base + 128 + r) & (SS-1))*DD + seg*4);
    }
    asm volatile("cp.async.commit_group;\n");
    asm volatile("cp.async.wait_group 0;\n");
    __syncthreads();

    // ---- scores: both halves, 8 n-tiles each ----
    float4 acc[2][8];
    #pragma unroll
    for (int i = 0; i < 2; i++)
        #pragma unroll
        for (int j = 0; j < 8; j++) acc[i][j] = make_float4(0.f,0.f,0.f,0.f);

    #pragma unroll 1
    for (int hf = 0; hf < 2; hf++) {
        const float* Bsrc = hf ? sK : sQ;
        #pragma unroll
        for (int ks = 0; ks < 8; ks++) {
            int kc = ks * 8;
            uint32_t a[4], bfr[8][2];
            a[0] = tf32u(sQ[(warp_m+g  )*QST + kc+tg  ]);
            a[1] = tf32u(sQ[(warp_m+g+8)*QST + kc+tg  ]);
            a[2] = tf32u(sQ[(warp_m+g  )*QST + kc+tg+4]);
            a[3] = tf32u(sQ[(warp_m+g+8)*QST + kc+tg+4]);
            #pragma unroll
            for (int nt = 0; nt < 8; nt++) {
                int n0 = warp_n + nt*8;
                bfr[nt][0] = tf32u(Bsrc[(n0+g)*QST + kc+tg  ]);
                bfr[nt][1] = tf32u(Bsrc[(n0+g)*QST + kc+tg+4]);
            }
            #pragma unroll
            for (int nt = 0; nt < 8; nt++)
                mma_tf32(acc[hf][nt], a[0],a[1],a[2],a[3], bfr[nt][0], bfr[nt][1]);
        }
    }

    // scale + self-mask (half0 only)
    int i0 = warp_m + g;
    #pragma unroll
    for (int hf = 0; hf < 2; hf++) {
        #pragma unroll
        for (int nt = 0; nt < 8; nt++) {
            int j0 = warp_n + nt*8 + 2*tg;
            float4 c = acc[hf][nt];
            c.x *= scale; c.y *= scale; c.z *= scale; c.w *= scale;
            if (hf == 0) {
                if (j0   == i0  ) c.x = -INFINITY;
                if (j0+1 == i0  ) c.y = -INFINITY;
                if (j0   == i0+8) c.z = -INFINITY;
                if (j0+1 == i0+8) c.w = -INFINITY;
            }
            acc[hf][nt] = c;
        }
    }
    __syncthreads();     // all warps done reading sQ/sK

    // V load overlaps softmax (overwrites sQ/sK region)
    for (int p = tid; p < 256*16; p += 512) {
        int j = p >> 4, seg = p & 15;
        cpa16(svb + (j*VST + seg*4)*4, vp + (size_t)((base + j) & (SS-1))*DD + seg*4);
    }
    asm volatile("cp.async.commit_group;\n");

    // ---- register softmax ----
    float* redM = red;
    float* redS = red + 256;
    float m0 = -INFINITY, m1 = -INFINITY;
    #pragma unroll
    for (int hf = 0; hf < 2; hf++)
        #pragma unroll
        for (int nt = 0; nt < 8; nt++) {
            float4 c = acc[hf][nt];
            m0 = fmaxf(m0, fmaxf(c.x, c.y));
            m1 = fmaxf(m1, fmaxf(c.z, c.w));
        }
    m0 = fmaxf(m0, __shfl_xor_sync(0xffffffffu, m0, 1));
    m0 = fmaxf(m0, __shfl_xor_sync(0xffffffffu, m0, 2));
    m1 = fmaxf(m1, __shfl_xor_sync(0xffffffffu, m1, 1));
    m1 = fmaxf(m1, __shfl_xor_sync(0xffffffffu, m1, 2));
    if (tg == 0) {
        redM[ng*128 + warp_m + g]     = m0;
        redM[ng*128 + warp_m + g + 8] = m1;
    }
    __syncthreads();
    float mg0 = fmaxf(redM[warp_m + g],     redM[128 + warp_m + g]);
    float mg1 = fmaxf(redM[warp_m + g + 8], redM[128 + warp_m + g + 8]);

    float s0 = 0.f, s1 = 0.f;
    #pragma unroll
    for (int hf = 0; hf < 2; hf++)
        #pragma unroll
        for (int nt = 0; nt < 8; nt++) {
            float4 c = acc[hf][nt];
            c.x = __expf(c.x - mg0); c.y = __expf(c.y - mg0);
            c.z = __expf(c.z - mg1); c.w = __expf(c.w - mg1);
            s0 += c.x + c.y; s1 += c.z + c.w;
            acc[hf][nt] = c;
        }
    s0 += __shfl_xor_sync(0xffffffffu, s0, 1);
    s0 += __shfl_xor_sync(0xffffffffu, s0, 2);
    s1 += __shfl_xor_sync(0xffffffffu, s1, 1);
    s1 += __shfl_xor_sync(0xffffffffu, s1, 2);
    if (tg == 0) {
        redS[ng*128 + warp_m + g]     = s0;
        redS[ng*128 + warp_m + g + 8] = s1;
    }
    __syncthreads();
    float inv0 = 1.f / (redS[warp_m + g]     + redS[128 + warp_m + g]);
    float inv1 = 1.f / (redS[warp_m + g + 8] + redS[128 + warp_m + g + 8]);

    // P = tf32r(p/sum), kept in REGISTERS
    #pragma unroll
    for (int hf = 0; hf < 2; hf++)
        #pragma unroll
        for (int nt = 0; nt < 8; nt++) {
            float4 c = acc[hf][nt];
            c.x = tf32r(c.x*inv0); c.y = tf32r(c.y*inv0);
            c.z = tf32r(c.z*inv1); c.w = tf32r(c.w*inv1);
            acc[hf][nt] = c;
        }

    asm volatile("cp.async.wait_group 0;\n");
    __syncthreads();   // V ready

    // ---- PV from registers: each warp sums its OWN 128 k-cols over 64 out cols ----
    float4 o[8];
    #pragma unroll
    for (int j = 0; j < 8; j++) o[j] = make_float4(0.f,0.f,0.f,0.f);

    int srcA = (lane & ~3) | (tg >> 1);
    int srcB = srcA + 2;
    bool odd = (tg & 1);

    #pragma unroll 1
    for (int hf = 0; hf < 2; hf++) {
        #pragma unroll
        for (int ks = 0; ks < 8; ks++) {
            float4 c = acc[hf][ks];
            // accumulator fragment -> A-operand fragment (cols 2tg,2tg+1 -> tg,tg+4)
            float x0 = __shfl_sync(0xffffffffu, c.x, srcA);
            float y0 = __shfl_sync(0xffffffffu, c.y, srcA);
            float z0 = __shfl_sync(0xffffffffu, c.z, srcA);
            float w0 = __shfl_sync(0xffffffffu, c.w, srcA);
            float x1 = __shfl_sync(0xffffffffu, c.x, srcB);
            float y1 = __shfl_sync(0xffffffffu, c.y, srcB);
            float z1 = __shfl_sync(0xffffffffu, c.z, srcB);
            float w1 = __shfl_sync(0xffffffffu, c.w, srcB);
            uint32_t a0 = __float_as_uint(odd ? y0 : x0);   // row g,   col tg
            uint32_t a1 = __float_as_uint(odd ? w0 : z0);   // row g+8, col tg
            uint32_t a2 = __float_as_uint(odd ? y1 : x1);   // row g,   col tg+4
            uint32_t a3 = __float_as_uint(odd ? w1 : z1);   // row g+8, col tg+4
            int j0q = hf*128 + warp_n + ks*8;               // global k offset
            #pragma unroll
            for (int nt = 0; nt < 8; nt++) {
                int n0 = nt*8;
                uint32_t b0 = tf32u(sV[(j0q+tg  )*VST + n0+g]);
                uint32_t b1 = tf32u(sV[(j0q+tg+4)*VST + n0+g]);
                mma_tf32(o[nt], a0,a1,a2,a3, b0,b1);
            }
        }
    }

    // ---- combine ng pairs via smem partials ----
    if (ng == 1) {
        #pragma unroll
        for (int nt = 0; nt < 8; nt++) {
            int d0 = nt*8 + 2*tg;
            *(float2*)&ps[(i0  )*PST + d0] = make_float2(o[nt].x, o[nt].y);
            *(float2*)&ps[(i0+8)*PST + d0] = make_float2(o[nt].z, o[nt].w);
        }
    }
    __syncthreads();
    if (ng == 0) {
        float* outp = g_outs + (size_t)b*SS*DD + h*DH;
        int t0 = base + i0;
        #pragma unroll
        for (int nt = 0; nt < 8; nt++) {
            int d0 = nt*8 + 2*tg;
            float2 p0 = *(float2*)&ps[(i0  )*PST + d0];
            float2 p1 = *(float2*)&ps[(i0+8)*PST + d0];
            float ox = o[nt].x + p0.x, oy = o[nt].y + p0.y;
            float oz = o[nt].z + p1.x, ow = o[nt].w + p1.y;
            *(float2*)(outp + (size_t)t0*DD + d0)     = make_float2(ox, oy);
            *(float2*)(outp + (size_t)(t0+8)*DD + d0) = make_float2(oz, ow);
            if (d0 == 0) {
                g_ch0[((size_t)b*SS + t0  )*HH + h] = ox;
                g_ch0[((size_t)b*SS + t0+8)*HH + h] = oz;
            }
        }
    }
}

// ---------------- 5) feature-0-only inverse scatter ----------------
__global__ void __launch_bounds__(256) scatter_kernel() {
    int i = blockIdx.x*256 + threadIdx.x;
    if (i >= BB*SS*HH) return;
    int h = i % HH;
    int b = i / (SS*HH);
    int p = g_idx[i];
    g_outs[((size_t)b*SS + p)*DD + h*DH] = g_ch0[i];
}

// ---------------- launch ----------------
extern "C" void kernel_launch(void* const* d_in, const int* in_sizes, int n_in,
                              void* d_out, int out_size) {
    const float* x  = (const float*)d_in[0];
    const float* Wh = (const float*)d_in[1];
    const float* Wq = (const float*)d_in[2];
    const float* bq = (const float*)d_in[3];
    const float* Wv = (const float*)d_in[4];
    const float* bv = (const float*)d_in[5];
    const float* Wo = (const float*)d_in[6];
    const float* bo = (const float*)d_in[7];
    float* out = (float*)d_out;

    float* qkp; cudaGetSymbolAddress((void**)&qkp, g_qk);
    float* vp;  cudaGetSymbolAddress((void**)&vp,  g_v);
    float* osp; cudaGetSymbolAddress((void**)&osp, g_outs);

    const int M = BB*SS;

    hash_kernel<<<M/32, 256>>>(x, Wh);
    sort_kernel<<<BB*HH, 1024>>>();

    size_t gsmem = (size_t)(4*128*AST) * sizeof(float);   // 73,728 B (2-stage)
    cudaFuncSetAttribute(gemm3, cudaFuncAttributeMaxDynamicSharedMemorySize, (int)gsmem);
    gemm3<<<dim3(16, M/128), 256, gsmem>>>(x, Wq, bq, qkp, Wv, bv, vp, 8, DD, DD, 1);

    size_t asmem = (size_t)(OVR + 128*PST + 512) * sizeof(float);   // 109,568 B
    cudaFuncSetAttribute(attn_kernel, cudaFuncAttributeMaxDynamicSharedMemorySize, (int)asmem);
    dim3 ag(NB, HH, BB);
    attn_kernel<<<ag, 512, asmem>>>();

    scatter_kernel<<<(BB*SS*HH + 255)/256, 256>>>();
    gemm3<<<dim3(8, M/128), 256, gsmem>>>(osp, Wo, bo, out, Wo, bo, out, 8, DD, DD, 0);
}